// round 6
// baseline (speedup 1.0000x reference)
#include <cuda_runtime.h>

#define NT 1096
#define NS 2048
#define NH 16
#define NC 8                 // time chunks
#define CL 137               // chunk length: 8*137 = 1096
#define NL (NS*NH)           // 32768 lanes

// Scratch (6 MB static device arrays; allocation-free rule)
__device__ float g_A[NC * NL];
__device__ float g_B[NC * NL];
__device__ float g_C[NC * NL];
__device__ float g_s0[NC * NL];
__device__ float g_hsum[NC * NL];
__device__ float g_hs0[NC * NL];

// ── P1: fold snow step-operators per chunk into f(s)=max(s-A,B)+C ──────────
__global__ __launch_bounds__(256)
void p1_snow_ops(const float* __restrict__ P, const float* __restrict__ T,
                 const float* __restrict__ w_s)
{
    const int g    = blockIdx.x * blockDim.x + threadIdx.x;   // c*NL + lane
    const int c    = g / NL;
    const int lane = g - c * NL;
    const int site = lane >> 4;
    const int h    = lane & 15;
    const float melt = expf(w_s[h]) + 1.0f;

    float A = 0.0f, B = -1e30f, C = 0.0f;
    const float* Pp = P + site;
    const float* Tp = T + site;
    const int t0 = c * CL;

    float Tk = Tp[(size_t)t0 * NS];
    float Pk = Pp[(size_t)t0 * NS];
    #pragma unroll 4
    for (int t = 0; t < CL; ++t) {
        float Tn = 0.0f, Pn = 0.0f;
        if (t + 1 < CL) {                       // prefetch next step
            Tn = Tp[(size_t)(t0 + t + 1) * NS];
            Pn = Pp[(size_t)(t0 + t + 1) * NS];
        }
        const float sm  = fmaxf(Tk, 0.0f) * melt;
        const float pin = (Tk < 0.0f) ? Pk : 0.0f;
        // compose step (sm, 0, pin) after accumulated (A,B,C)
        const float An = A + sm - C;
        const float Bn = fmaxf(B + C - sm, 0.0f);
        A = An; B = Bn; C = pin;
        Tk = Tn; Pk = Pn;
    }
    g_A[g] = A; g_B[g] = B; g_C[g] = C;
}

// ── P2: tiny scan of chunk operators -> incoming snow state per chunk ──────
__global__ __launch_bounds__(256)
void p2_scan_s0()
{
    const int lane = blockIdx.x * blockDim.x + threadIdx.x;
    float s = 0.0f;
    #pragma unroll
    for (int c = 0; c < NC; ++c) {
        const int idx = c * NL + lane;
        g_s0[idx] = s;
        s = fmaxf(s - g_A[idx], g_B[idx]) + g_C[idx];
    }
}

// ── P3: replay snow per chunk from exact s0; fold linear bucket (hs0=0) ────
__global__ __launch_bounds__(256)
void p3_hsum(const float* __restrict__ P, const float* __restrict__ T,
             const float* __restrict__ w_i, const float* __restrict__ w_l,
             const float* __restrict__ w_s)
{
    const int g    = blockIdx.x * blockDim.x + threadIdx.x;
    const int c    = g / NL;
    const int lane = g - c * NL;
    const int site = lane >> 4;
    const int h    = lane & 15;

    const float melt  = expf(w_s[h]) + 1.0f;
    const float gi    = 1.0f / (1.0f + expf(-w_i[h]));
    const float gl    = 1.0f / (1.0f + expf(-w_l[h]));
    const float alpha = 1.0f - gl;
    const float gax   = alpha * gi;

    float s  = g_s0[g];
    float hl = 0.0f;
    const float* Pp = P + site;
    const float* Tp = T + site;
    const int t0 = c * CL;

    float Tk = Tp[(size_t)t0 * NS];
    float Pk = Pp[(size_t)t0 * NS];
    #pragma unroll 4
    for (int t = 0; t < CL; ++t) {
        float Tn = 0.0f, Pn = 0.0f;
        if (t + 1 < CL) {
            Tn = Tp[(size_t)(t0 + t + 1) * NS];
            Pn = Pp[(size_t)(t0 + t + 1) * NS];
        }
        const float sm   = fmaxf(Tk, 0.0f) * melt;
        const float m    = fminf(sm, s);
        const float pin  = (Tk < 0.0f) ? Pk : 0.0f;
        const float rain = (Tk > 0.0f) ? Pk : 0.0f;
        s = (s - m) + pin;
        const float x = rain + m;
        hl = alpha * hl + gax * x;
        Tk = Tn; Pk = Pn;
    }
    g_hsum[g] = hl;
}

// ── P4: tiny scan of linear-bucket state across chunks ─────────────────────
__global__ __launch_bounds__(256)
void p4_scan_hs0(const float* __restrict__ w_l)
{
    const int lane = blockIdx.x * blockDim.x + threadIdx.x;
    const int h    = lane & 15;
    const float gl    = 1.0f / (1.0f + expf(-w_l[h]));
    const float alpha = 1.0f - gl;
    const float aL    = powf(alpha, (float)CL);

    float hs = 0.0f;
    #pragma unroll
    for (int c = 0; c < NC; ++c) {
        const int idx = c * NL + lane;
        g_hs0[idx] = hs;
        hs = aL * hs + g_hsum[idx];
    }
}

// ── P5: full replay from exact (s0, hs0); write Q, H, S ────────────────────
__global__ __launch_bounds__(256)
void p5_final(const float* __restrict__ P, const float* __restrict__ T,
              const float* __restrict__ w_i, const float* __restrict__ w_o,
              const float* __restrict__ w_l, const float* __restrict__ w_s,
              float* __restrict__ Q, float* __restrict__ H, float* __restrict__ S)
{
    const int g    = blockIdx.x * blockDim.x + threadIdx.x;
    const int c    = g / NL;
    const int lane = g - c * NL;
    const int site = lane >> 4;
    const int h    = lane & 15;

    const float melt  = expf(w_s[h]) + 1.0f;
    const float gi    = 1.0f / (1.0f + expf(-w_i[h]));
    const float gl    = 1.0f / (1.0f + expf(-w_l[h]));
    float wmax = w_o[0];
    #pragma unroll
    for (int i = 1; i < NH; ++i) wmax = fmaxf(wmax, w_o[i]);
    float denom = 0.0f;
    #pragma unroll
    for (int i = 0; i < NH; ++i) denom += expf(w_o[i] - wmax);
    const float a = expf(w_o[h] - wmax) / denom;

    const float alpha = 1.0f - gl;
    const float gax   = alpha * gi;
    const float ch    = a * gl / alpha;   // q*a = hs_new * ch

    float s  = g_s0[g];
    float hs = g_hs0[g];

    const float* Pp = P + site;
    const float* Tp = T + site;
    float* Hp = H + lane;
    float* Sp = S + lane;
    float* Qp = Q + site;
    const int t0 = c * CL;

    float Tk = Tp[(size_t)t0 * NS];
    float Pk = Pp[(size_t)t0 * NS];
    for (int t = 0; t < CL; ++t) {
        float Tn = 0.0f, Pn = 0.0f;
        if (t + 1 < CL) {
            Tn = Tp[(size_t)(t0 + t + 1) * NS];
            Pn = Pp[(size_t)(t0 + t + 1) * NS];
        }
        const float sm   = fmaxf(Tk, 0.0f) * melt;
        const float m    = fminf(sm, s);
        const float pin  = (Tk < 0.0f) ? Pk : 0.0f;
        const float rain = (Tk > 0.0f) ? Pk : 0.0f;
        s = (s - m) + pin;
        const float x = rain + m;
        hs = alpha * hs + gax * x;

        const size_t off = (size_t)(t0 + t) * (size_t)NL;
        Hp[off] = hs;
        Sp[off] = s;

        float qa = hs * ch;
        qa += __shfl_xor_sync(0xffffffffu, qa, 1);
        qa += __shfl_xor_sync(0xffffffffu, qa, 2);
        qa += __shfl_xor_sync(0xffffffffu, qa, 4);
        qa += __shfl_xor_sync(0xffffffffu, qa, 8);
        if (h == 0) Qp[(size_t)(t0 + t) * NS] = qa;

        Tk = Tn; Pk = Pn;
    }
}

extern "C" void kernel_launch(void* const* d_in, const int* in_sizes, int n_in,
                              void* d_out, int out_size) {
    const float* P   = (const float*)d_in[0];
    const float* T   = (const float*)d_in[1];
    const float* w_i = (const float*)d_in[2];
    const float* w_o = (const float*)d_in[3];
    const float* w_l = (const float*)d_in[4];
    const float* w_s = (const float*)d_in[5];

    float* out = (float*)d_out;
    float* Q = out;                                           // [NT, NS]
    float* H = out + (size_t)NT * NS;                         // [NT, NS, NH]
    float* S = out + (size_t)NT * NS + (size_t)NT * NS * NH;  // [NT, NS, NH]

    const int big = NC * NL;            // 262144 threads
    p1_snow_ops<<<big / 256, 256>>>(P, T, w_s);
    p2_scan_s0 <<<NL / 256, 256>>>();
    p3_hsum    <<<big / 256, 256>>>(P, T, w_i, w_l, w_s);
    p4_scan_hs0<<<NL / 256, 256>>>(w_l);
    p5_final   <<<big / 256, 256>>>(P, T, w_i, w_o, w_l, w_s, Q, H, S);
}